// round 10
// baseline (speedup 1.0000x reference)
#include <cuda_runtime.h>

// Slice_windows: (32,1,1024,1024) f32 -> (32,8) f32
//
// R8 = R1 main kernel EXACTLY (unroll 4, ternary plogp — empirically the
// fastest streaming codegen: ~26.7us) + fused finalize tail only.
//  - One CTA per 256x256 tile (512 CTAs, 512 threads, occ 2).
//  - Gmem pass: k=2 sums+entropy in registers, 128x128 sums -> smem.
//  - Smem pyramid k=4..256.
//  - Last-arriving CTA reduces the 512x8 partials in fixed order.

#define NLEVELS 8
#define TILES_PER_IMG 16
#define NBATCH 32
#define NBLOCKS (NBATCH * TILES_PER_IMG)
#define NTHREADS 512

// pyramid: 128^2 + 64^2 + ... + 1 = 21845 floats
#define SMEM_FLOATS 21845
#define SMEM_BYTES (SMEM_FLOATS * 4)

__device__ float g_partials[NBLOCKS * NLEVELS];
__device__ int   g_count = 0;

__device__ __forceinline__ float plogp(float p) {
    // p * log2(p), 0 at p == 0
    return (p > 0.f) ? p * __log2f(p) : 0.f;
}

__global__ void __launch_bounds__(NTHREADS, 2)
slice_windows_fused(const float* __restrict__ x, float* __restrict__ out)
{
    extern __shared__ float sm[];
    __shared__ bool is_last;

    const int tid  = threadIdx.x;
    const int bid  = blockIdx.x;
    const int b    = bid >> 4;
    const int tile = bid & 15;
    const int row0 = (tile >> 2) * 256;
    const int col0 = (tile & 3) * 256;
    const float* __restrict__ img = x + (size_t)b * 1024 * 1024;

    float eacc[NLEVELS];
#pragma unroll
    for (int l = 0; l < NLEVELS; l++) eacc[l] = 0.f;

    // ---- Level 0 (k=2): read gmem tile, write 128x128 sums to sm[0..16383]
    {
        const float inv_n = 0.25f;
        const int r  = tid >> 6;   // 0..7 : output row within iteration group
        const int c4 = tid & 63;   // each thread: 2 outputs via float4 per row
#pragma unroll 4
        for (int it = 0; it < 16; ++it) {
            const int orow = it * 8 + r;            // 0..127
            const int grow = row0 + orow * 2;
            const float4 a0 = *((const float4*)(img + (size_t)grow * 1024 + col0) + c4);
            const float4 a1 = *((const float4*)(img + (size_t)(grow + 1) * 1024 + col0) + c4);
            const float s0 = (a0.x + a0.y) + (a1.x + a1.y);
            const float s1 = (a0.z + a0.w) + (a1.z + a1.w);
            const float p0 = s0 * inv_n;
            const float p1 = s1 * inv_n;
            eacc[0] -= plogp(p0) + plogp(1.f - p0);
            eacc[0] -= plogp(p1) + plogp(1.f - p1);
            sm[orow * 128 + c4 * 2]     = s0;
            sm[orow * 128 + c4 * 2 + 1] = s1;
        }
    }
    __syncthreads();

    // ---- Levels 1..7: pyramid reduction in smem
    int in_off = 0, in_dim = 128, out_off = 16384;
#pragma unroll
    for (int l = 1; l < NLEVELS; l++) {
        const int out_dim = in_dim >> 1;
        const int nout = out_dim * out_dim;
        const float inv_n = 1.0f / (float)(1 << (2 * (l + 1)));  // 1/k^2, k=2^(l+1)
        for (int i = tid; i < nout; i += NTHREADS) {
            const int oy = i / out_dim;
            const int ox = i - oy * out_dim;
            const float* rp0 = sm + in_off + (2 * oy) * in_dim + 2 * ox;
            const float* rp1 = rp0 + in_dim;
            const float s = (rp0[0] + rp0[1]) + (rp1[0] + rp1[1]);
            const float p = s * inv_n;
            eacc[l] -= plogp(p) + plogp(1.f - p);
            sm[out_off + i] = s;
        }
        __syncthreads();
        in_off = out_off;
        in_dim = out_dim;
        out_off += nout;
    }
    // after final sync, level-0 smem region is dead -> reuse for reduction

    // ---- Block-reduce the 8 per-thread entropy accumulators
    const int lane = tid & 31;
    const int warp = tid >> 5;   // 16 warps
#pragma unroll
    for (int l = 0; l < NLEVELS; l++) {
        float v = eacc[l];
#pragma unroll
        for (int o = 16; o > 0; o >>= 1)
            v += __shfl_down_sync(0xffffffffu, v, o);
        if (lane == 0) sm[warp * NLEVELS + l] = v;
    }
    __syncthreads();
    if (tid < NLEVELS) {
        float s = 0.f;
#pragma unroll
        for (int w = 0; w < 16; w++) s += sm[w * NLEVELS + tid];
        g_partials[bid * NLEVELS + tid] = s;
    }

    // ---- Fused finalize: last-arriving CTA reduces all partials
    __threadfence();
    if (tid == 0) {
        const int prev = atomicAdd(&g_count, 1);
        is_last = (prev == NBLOCKS - 1);
    }
    __syncthreads();
    if (is_last) {
        if (tid < NBATCH * NLEVELS) {
            const int bb = tid >> 3;
            const int l  = tid & 7;
            float s = 0.f;
#pragma unroll
            for (int t = 0; t < TILES_PER_IMG; t++)
                s += __ldcg(&g_partials[(bb * TILES_PER_IMG + t) * NLEVELS + l]);
            const int d = 1024 >> (l + 1);   // windows per side, k = 2^(l+1)
            out[bb * NLEVELS + l] = s / (float)(d * d);
        }
        if (tid == 0) g_count = 0;           // reset for graph replay
    }
}

extern "C" void kernel_launch(void* const* d_in, const int* in_sizes, int n_in,
                              void* d_out, int out_size)
{
    (void)in_sizes; (void)n_in; (void)out_size;
    const float* x = (const float*)d_in[0];
    float* out = (float*)d_out;

    cudaFuncSetAttribute(slice_windows_fused,
                         cudaFuncAttributeMaxDynamicSharedMemorySize, SMEM_BYTES);
    slice_windows_fused<<<NBLOCKS, NTHREADS, SMEM_BYTES>>>(x, out);
}